// round 12
// baseline (speedup 1.0000x reference)
#include <cuda_runtime.h>
#include <cuda_bf16.h>
#include <math.h>
#include <stdint.h>
#include <cstdint>

#define N_NODES 10000
#define N_EDGES 160000
#define N_FEAT  512
#define HEADS   8
#define HID     128
#define NH      (HEADS * HID)   // 1024

// ---------------- scratch (device globals; no allocations allowed) ----------
__device__ __nv_bfloat16 g_hb[(size_t)N_NODES * NH]; // projected features bf16
__device__ float g_emb1[(size_t)N_NODES * HID];      // tf32-rounded at write
__device__ float g_emb2[(size_t)N_NODES * HID];
__device__ float g_xr[(size_t)N_NODES * N_FEAT];     // tf32-rounded x
__device__ float g_wr1[NH * N_FEAT];                 // tf32-rounded W1
__device__ float g_wr2[NH * HID];                    // tf32-rounded W2
__device__ float g_si[N_NODES * HEADS];
__device__ float g_sj[N_NODES * HEADS];
__device__ int   g_deg[N_NODES];     // zero at entry; scan re-zeroes after use
__device__ int   g_off[N_NODES + 1];
__device__ int   g_cur[N_NODES];
__device__ int   g_csr[N_EDGES];
__device__ float g_gvec[HID];        // zero at entry; mlp re-zeroes after use

__device__ __forceinline__ unsigned cvt_tf32(float f) {
    unsigned u;
    asm("cvt.rna.tf32.f32 %0, %1;" : "=r"(u) : "f"(f));
    return u;
}

// ---------------- tf32 pre-rounding ----------------
__global__ void round_tf32_kernel(const float* __restrict__ src, float* __restrict__ dst, int n4) {
    int i = blockIdx.x * blockDim.x + threadIdx.x;
    if (i < n4) {
        float4 v = reinterpret_cast<const float4*>(src)[i];
        v.x = __uint_as_float(cvt_tf32(v.x));
        v.y = __uint_as_float(cvt_tf32(v.y));
        v.z = __uint_as_float(cvt_tf32(v.z));
        v.w = __uint_as_float(cvt_tf32(v.w));
        reinterpret_cast<float4*>(dst)[i] = v;
    }
}

// ---------------- CSR construction ----------------
__global__ void hist_kernel(const int* __restrict__ dst) {
    int e = blockIdx.x * blockDim.x + threadIdx.x;
    if (e < N_EDGES) atomicAdd(&g_deg[dst[e]], 1);
}

__global__ void scan_kernel() {
    __shared__ int sums[1024];
    int t = threadIdx.x;
    const int CH = (N_NODES + 1023) / 1024;   // 10
    int start = t * CH;
    int dloc[CH];
    int s = 0;
    for (int i = 0; i < CH; i++) {
        int idx = start + i;
        dloc[i] = (idx < N_NODES) ? g_deg[idx] : 0;
        s += dloc[i];
    }
    sums[t] = s;
    __syncthreads();
    for (int st = 1; st < 1024; st <<= 1) {
        int v = (t >= st) ? sums[t - st] : 0;
        __syncthreads();
        sums[t] += v;
        __syncthreads();
    }
    int base = (t == 0) ? 0 : sums[t - 1];
    for (int i = 0; i < CH; i++) {
        int idx = start + i;
        if (idx < N_NODES) {
            g_off[idx] = base;
            g_cur[idx] = base;
            base += dloc[i];
            g_deg[idx] = 0;          // restore invariant for next call
        }
    }
    if (t == 1023) g_off[N_NODES] = sums[1023];
}

__global__ void fill_kernel(const int* __restrict__ src, const int* __restrict__ dst) {
    int e = blockIdx.x * blockDim.x + threadIdx.x;
    if (e < N_EDGES) {
        int pos = atomicAdd(&g_cur[dst[e]], 1);
        g_csr[pos] = src[e];
    }
}

// ---------------- TF32 GEMM (pre-rounded inputs, no in-loop CVT) -----------
// C[m,n] = sum_k A[m,k]*B[n,k]. Block tile 128x128 (one head per x-block),
// 256 threads = 8 warps (4x2), warp tile 32x64, BK=16 double-buffered
// cp.async. Epilogue: bf16 h -> g_hb; s_i/s_j via smem -> plain stores.
#define GBM 128
#define GBN 128
#define GBK 16

__device__ __forceinline__ int swoff(int m, int k) {
    return m * GBK + ((((k >> 2) ^ (m >> 1)) & 3) << 2) + (k & 3);
}

__device__ __forceinline__ void mma_tf32(float* c, const unsigned* a, const unsigned* b) {
    asm volatile(
        "mma.sync.aligned.m16n8k8.row.col.f32.tf32.tf32.f32 "
        "{%0,%1,%2,%3}, {%4,%5,%6,%7}, {%8,%9}, {%0,%1,%2,%3};"
        : "+f"(c[0]), "+f"(c[1]), "+f"(c[2]), "+f"(c[3])
        : "r"(a[0]), "r"(a[1]), "r"(a[2]), "r"(a[3]), "r"(b[0]), "r"(b[1]));
}

template<bool LAYER1>
__global__ __launch_bounds__(256)
void gemm_tf32(const float* __restrict__ av, int M, int N, int K) {
    const float* A = LAYER1 ? g_xr  : g_emb1;
    const float* B = LAYER1 ? g_wr1 : g_wr2;

    __shared__ float As[2][GBM * GBK];
    __shared__ float Bs[2][GBM * GBK];
    __shared__ float sh_a[2 * HID];
    __shared__ float sc_i[GBM];
    __shared__ float sc_j[GBM];

    int tid = threadIdx.x;
    int lane = tid & 31;
    int wid = tid >> 5;
    int wm = wid & 3;          // 0..3
    int wn = wid >> 2;         // 0..1
    int bm = blockIdx.y * GBM;
    int bn = blockIdx.x * GBN;
    int head = blockIdx.x;     // GBN == HID => one head per x-block

    if (tid < 2 * HID) sh_a[tid] = av[head * 2 * HID + tid];
    if (tid < GBM) { sc_i[tid] = 0.f; sc_j[tid] = 0.f; }

    unsigned sA = (unsigned)__cvta_generic_to_shared(&As[0][0]);
    unsigned sB = (unsigned)__cvta_generic_to_shared(&Bs[0][0]);

    float acc[2][8][4];
    #pragma unroll
    for (int mi = 0; mi < 2; mi++)
        #pragma unroll
        for (int ni = 0; ni < 8; ni++)
            #pragma unroll
            for (int r = 0; r < 4; r++) acc[mi][ni][r] = 0.f;

    const int nch = K / GBK;

    auto load_tile = [&](int c, int s) {
        #pragma unroll
        for (int i = 0; i < 2; i++) {
            int id  = tid + i * 256;     // 0..511
            int row = id >> 2;           // 0..127
            int g   = id & 3;
            int soff = (s * (GBM * GBK) + row * GBK + (((g ^ (row >> 1)) & 3) << 2)) << 2;
            {
                int gm = bm + row;
                const float* src = A + (size_t)(gm < M ? gm : (M - 1)) * K + c * GBK + g * 4;
                int sz = (gm < M) ? 16 : 0;
                asm volatile("cp.async.cg.shared.global [%0], [%1], 16, %2;\n"
                             :: "r"(sA + soff), "l"(src), "r"(sz));
            }
            {
                const float* src = B + (size_t)(bn + row) * K + c * GBK + g * 4;
                asm volatile("cp.async.cg.shared.global [%0], [%1], 16;\n"
                             :: "r"(sB + soff), "l"(src));
            }
        }
    };

    load_tile(0, 0);
    asm volatile("cp.async.commit_group;\n");

    for (int c = 0; c < nch; c++) {
        int buf = c & 1;
        if (c + 1 < nch) {
            load_tile(c + 1, buf ^ 1);
            asm volatile("cp.async.commit_group;\n");
            asm volatile("cp.async.wait_group 1;\n");
        } else {
            asm volatile("cp.async.wait_group 0;\n");
        }
        __syncthreads();

        #pragma unroll
        for (int ks = 0; ks < GBK / 8; ks++) {
            int kk = ks * 8 + (lane & 3);
            unsigned af[2][4];
            #pragma unroll
            for (int mi = 0; mi < 2; mi++) {
                int m0 = wm * 32 + mi * 16 + (lane >> 2);
                int m1 = m0 + 8;
                af[mi][0] = __float_as_uint(As[buf][swoff(m0, kk)]);
                af[mi][1] = __float_as_uint(As[buf][swoff(m1, kk)]);
                af[mi][2] = __float_as_uint(As[buf][swoff(m0, kk + 4)]);
                af[mi][3] = __float_as_uint(As[buf][swoff(m1, kk + 4)]);
            }
            unsigned bf[8][2];
            #pragma unroll
            for (int ni = 0; ni < 8; ni++) {
                int n0 = wn * 64 + ni * 8 + (lane >> 2);
                bf[ni][0] = __float_as_uint(Bs[buf][swoff(n0, kk)]);
                bf[ni][1] = __float_as_uint(Bs[buf][swoff(n0, kk + 4)]);
            }
            #pragma unroll
            for (int mi = 0; mi < 2; mi++)
                #pragma unroll
                for (int ni = 0; ni < 8; ni++)
                    mma_tf32(acc[mi][ni], af[mi], bf[ni]);
        }
        __syncthreads();
    }

    // ---- epilogue: bf16 store + fused score partials -----------------------
    float sco[2][4];   // per mi: si(m0), si(m1), sj(m0), sj(m1)
    #pragma unroll
    for (int mi = 0; mi < 2; mi++)
        #pragma unroll
        for (int r = 0; r < 4; r++) sco[mi][r] = 0.f;

    #pragma unroll
    for (int mi = 0; mi < 2; mi++) {
        int m0 = bm + wm * 32 + mi * 16 + (lane >> 2);
        int m1 = m0 + 8;
        #pragma unroll
        for (int ni = 0; ni < 8; ni++) {
            int dloc = wn * 64 + ni * 8 + (lane & 3) * 2;   // 0..127 within head
            float ai0 = sh_a[dloc],       ai1 = sh_a[dloc + 1];
            float aj0 = sh_a[HID + dloc], aj1 = sh_a[HID + dloc + 1];
            sco[mi][0] += acc[mi][ni][0] * ai0 + acc[mi][ni][1] * ai1;
            sco[mi][1] += acc[mi][ni][2] * ai0 + acc[mi][ni][3] * ai1;
            sco[mi][2] += acc[mi][ni][0] * aj0 + acc[mi][ni][1] * aj1;
            sco[mi][3] += acc[mi][ni][2] * aj0 + acc[mi][ni][3] * aj1;
            int nc = bn + dloc;
            if (m0 < M) {
                __nv_bfloat162 hb = __floats2bfloat162_rn(acc[mi][ni][0], acc[mi][ni][1]);
                *reinterpret_cast<__nv_bfloat162*>(&g_hb[(size_t)m0 * N + nc]) = hb;
            }
            if (m1 < M) {
                __nv_bfloat162 hb = __floats2bfloat162_rn(acc[mi][ni][2], acc[mi][ni][3]);
                *reinterpret_cast<__nv_bfloat162*>(&g_hb[(size_t)m1 * N + nc]) = hb;
            }
        }
    }

    #pragma unroll
    for (int mi = 0; mi < 2; mi++)
        #pragma unroll
        for (int r = 0; r < 4; r++) {
            sco[mi][r] += __shfl_xor_sync(0xffffffffu, sco[mi][r], 1);
            sco[mi][r] += __shfl_xor_sync(0xffffffffu, sco[mi][r], 2);
        }

    if ((lane & 3) == 0) {
        #pragma unroll
        for (int mi = 0; mi < 2; mi++) {
            int r0 = wm * 32 + mi * 16 + (lane >> 2);
            int r1 = r0 + 8;
            atomicAdd(&sc_i[r0], sco[mi][0]);
            atomicAdd(&sc_i[r1], sco[mi][1]);
            atomicAdd(&sc_j[r0], sco[mi][2]);
            atomicAdd(&sc_j[r1], sco[mi][3]);
        }
    }
    __syncthreads();

    if (tid < GBM) {
        int gm = bm + tid;
        if (gm < M) {
            g_si[gm * HEADS + head] = sc_i[tid];
            g_sj[gm * HEADS + head] = sc_j[tid];
        }
    }
}

// ---------------- aggregation: single-pass softmax + bf16 gather -----------
template<int OUT>
__global__ __launch_bounds__(256)
void aggregate_kernel() {
    int n = blockIdx.x;
    int w = threadIdx.x >> 5;
    int lane = threadIdx.x & 31;
    __shared__ float part[HEADS][HID];

    int off = g_off[n], end = g_off[n + 1];
    float si_v = g_si[n * HEADS + w];
    float4 acc = make_float4(0.f, 0.f, 0.f, 0.f);
    float dl = 0.f;

    for (int base = off; base < end; base += 32) {
        int e = base + lane;
        int src = 0;
        float p = 0.f;
        if (e < end) {
            src = g_csr[e];
            float x = si_v + g_sj[src * HEADS + w];
            float ev = (x > 0.f) ? x : 0.01f * x;
            p = __expf(ev);
            dl += p;
        }

        int cnt = min(32, end - base);
        const size_t lofs = (size_t)lane * 4;
        int j = 0;
        for (; j + 4 <= cnt; j += 4) {
            float p0 = __shfl_sync(0xffffffffu, p, j);
            float p1 = __shfl_sync(0xffffffffu, p, j + 1);
            float p2 = __shfl_sync(0xffffffffu, p, j + 2);
            float p3 = __shfl_sync(0xffffffffu, p, j + 3);
            int s0 = __shfl_sync(0xffffffffu, src, j);
            int s1 = __shfl_sync(0xffffffffu, src, j + 1);
            int s2 = __shfl_sync(0xffffffffu, src, j + 2);
            int s3 = __shfl_sync(0xffffffffu, src, j + 3);
            uint2 u0 = *reinterpret_cast<const uint2*>(&g_hb[((size_t)s0 * HEADS + w) * HID + lofs]);
            uint2 u1 = *reinterpret_cast<const uint2*>(&g_hb[((size_t)s1 * HEADS + w) * HID + lofs]);
            uint2 u2 = *reinterpret_cast<const uint2*>(&g_hb[((size_t)s2 * HEADS + w) * HID + lofs]);
            uint2 u3 = *reinterpret_cast<const uint2*>(&g_hb[((size_t)s3 * HEADS + w) * HID + lofs]);
            float2 a0 = __bfloat1622float2(*reinterpret_cast<__nv_bfloat162*>(&u0.x));
            float2 b0 = __bfloat1622float2(*reinterpret_cast<__nv_bfloat162*>(&u0.y));
            float2 a1 = __bfloat1622float2(*reinterpret_cast<__nv_bfloat162*>(&u1.x));
            float2 b1 = __bfloat1622float2(*reinterpret_cast<__nv_bfloat162*>(&u1.y));
            float2 a2f = __bfloat1622float2(*reinterpret_cast<__nv_bfloat162*>(&u2.x));
            float2 b2 = __bfloat1622float2(*reinterpret_cast<__nv_bfloat162*>(&u2.y));
            float2 a3 = __bfloat1622float2(*reinterpret_cast<__nv_bfloat162*>(&u3.x));
            float2 b3 = __bfloat1622float2(*reinterpret_cast<__nv_bfloat162*>(&u3.y));
            acc.x += p0 * a0.x + p1 * a1.x + p2 * a2f.x + p3 * a3.x;
            acc.y += p0 * a0.y + p1 * a1.y + p2 * a2f.y + p3 * a3.y;
            acc.z += p0 * b0.x + p1 * b1.x + p2 * b2.x  + p3 * b3.x;
            acc.w += p0 * b0.y + p1 * b1.y + p2 * b2.y  + p3 * b3.y;
        }
        for (; j < cnt; j++) {
            float pj = __shfl_sync(0xffffffffu, p, j);
            int sj = __shfl_sync(0xffffffffu, src, j);
            uint2 u = *reinterpret_cast<const uint2*>(&g_hb[((size_t)sj * HEADS + w) * HID + lofs]);
            float2 f0 = __bfloat1622float2(*reinterpret_cast<__nv_bfloat162*>(&u.x));
            float2 f1 = __bfloat1622float2(*reinterpret_cast<__nv_bfloat162*>(&u.y));
            acc.x += pj * f0.x; acc.y += pj * f0.y;
            acc.z += pj * f1.x; acc.w += pj * f1.y;
        }
    }

    #pragma unroll
    for (int o = 16; o; o >>= 1) dl += __shfl_xor_sync(0xffffffffu, dl, o);

    if (dl > 0.f) {
        float inv = 1.f / dl;
        acc.x *= inv; acc.y *= inv; acc.z *= inv; acc.w *= inv;
    }
    part[w][lane * 4 + 0] = acc.x;
    part[w][lane * 4 + 1] = acc.y;
    part[w][lane * 4 + 2] = acc.z;
    part[w][lane * 4 + 3] = acc.w;
    __syncthreads();

    if (threadIdx.x < HID) {
        int d = threadIdx.x;
        float s = 0.f;
        #pragma unroll
        for (int hh = 0; hh < HEADS; hh++) s += part[hh][d];
        s *= (1.f / HEADS);
        float o = (s > 0.f) ? s : (__expf(s) - 1.f);   // ELU
        if (OUT == 1) {
            // emb1 feeds GEMM2's A operand: pre-round to tf32 (rna) here
            o = __uint_as_float(cvt_tf32(o));
            g_emb1[(size_t)n * HID + d] = o;
        } else {
            g_emb2[(size_t)n * HID + d] = o;
        }
    }
}

// ---------------- graph mean pooling (one kernel, atomic combine) ----------
__global__ void pool_kernel() {
    const int RP = (N_NODES + 127) / 128;   // 79
    int b = blockIdx.x, d = threadIdx.x;
    int r0 = b * RP;
    int r1 = min(r0 + RP, N_NODES);
    float s = 0.f;
    for (int r = r0; r < r1; r++) s += g_emb2[(size_t)r * HID + d];
    atomicAdd(&g_gvec[d], s * (1.f / N_NODES));
}

// ---------------- MLP head ----------------
__global__ void mlp_kernel(const float* __restrict__ ln_g, const float* __restrict__ ln_b,
                           const float* __restrict__ Wl1, const float* __restrict__ bl1,
                           const float* __restrict__ Wl2, const float* __restrict__ bl2,
                           const float* __restrict__ Wl3, const float* __restrict__ bl3,
                           float* __restrict__ out) {
    __shared__ float gn[HID];
    __shared__ float x1[64];
    __shared__ float x2[16];
    __shared__ float red[128];
    int t = threadIdx.x;  // 128 threads
    float gv = g_gvec[t];
    g_gvec[t] = 0.f;      // restore invariant for next call

    red[t] = gv;
    __syncthreads();
    for (int st = 64; st; st >>= 1) {
        if (t < st) red[t] += red[t + st];
        __syncthreads();
    }
    float mu = red[0] * (1.f / HID);
    __syncthreads();

    float dv = gv - mu;
    red[t] = dv * dv;
    __syncthreads();
    for (int st = 64; st; st >>= 1) {
        if (t < st) red[t] += red[t + st];
        __syncthreads();
    }
    float var = red[0] * (1.f / HID);
    gn[t] = dv * rsqrtf(var + 1e-5f) * ln_g[t] + ln_b[t];
    __syncthreads();

    if (t < 64) {
        float s = bl1[t];
        for (int k = 0; k < HID; k++) s += Wl1[t * HID + k] * gn[k];
        x1[t] = (s > 0.f) ? s : 0.01f * s;
    }
    __syncthreads();
    if (t < 16) {
        float s = bl2[t];
        for (int k = 0; k < 64; k++) s += Wl2[t * 64 + k] * x1[k];
        x2[t] = (s > 0.f) ? s : 0.01f * s;
    }
    __syncthreads();
    if (t < 16) {
        float s = bl3[t];
        for (int k = 0; k < 16; k++) s += Wl3[t * 16 + k] * x2[k];
        out[t] = fmaxf(s, 0.f);
    }
}

// ---------------- launch ----------------
extern "C" void kernel_launch(void* const* d_in, const int* in_sizes, int n_in,
                              void* d_out, int out_size) {
    const float* x    = (const float*)d_in[0];
    const int*   esrc = (const int*)  d_in[1];
    const int*   edst = (const int*)  d_in[2];
    const float* W1   = (const float*)d_in[3];
    const float* a1   = (const float*)d_in[4];
    const float* W2   = (const float*)d_in[5];
    const float* a2   = (const float*)d_in[6];
    const float* ln_g = (const float*)d_in[7];
    const float* ln_b = (const float*)d_in[8];
    const float* Wl1  = (const float*)d_in[9];
    const float* bl1  = (const float*)d_in[10];
    const float* Wl2  = (const float*)d_in[11];
    const float* bl2  = (const float*)d_in[12];
    const float* Wl3  = (const float*)d_in[13];
    const float* bl3  = (const float*)d_in[14];
    float* out = (float*)d_out;

    float *xr_p, *wr1_p, *wr2_p;
    cudaGetSymbolAddress((void**)&xr_p,  g_xr);
    cudaGetSymbolAddress((void**)&wr1_p, g_wr1);
    cudaGetSymbolAddress((void**)&wr2_p, g_wr2);

    // tf32 pre-rounding (rna) of GEMM inputs
    round_tf32_kernel<<<(N_NODES * N_FEAT / 4 + 255) / 256, 256>>>(x,  xr_p,  N_NODES * N_FEAT / 4);
    round_tf32_kernel<<<(NH * N_FEAT / 4 + 255) / 256, 256>>>(W1, wr1_p, NH * N_FEAT / 4);
    round_tf32_kernel<<<(NH * HID / 4 + 255) / 256, 256>>>(W2, wr2_p, NH * HID / 4);

    // CSR build (g_deg is zero at entry; scan restores it)
    hist_kernel<<<(N_EDGES + 255) / 256, 256>>>(edst);
    scan_kernel<<<1, 1024>>>();
    fill_kernel<<<(N_EDGES + 255) / 256, 256>>>(esrc, edst);

    dim3 ggrid(NH / GBN, (N_NODES + GBM - 1) / GBM);   // (8, 79)

    // Layer 1
    gemm_tf32<true><<<ggrid, 256>>>(a1, N_NODES, NH, N_FEAT);
    aggregate_kernel<1><<<N_NODES, 256>>>();

    // Layer 2
    gemm_tf32<false><<<ggrid, 256>>>(a2, N_NODES, NH, HID);
    aggregate_kernel<2><<<N_NODES, 256>>>();

    // Pool + head
    pool_kernel<<<128, 128>>>();
    mlp_kernel<<<1, 128>>>(ln_g, ln_b, Wl1, bl1, Wl2, bl2, Wl3, bl3, out);
}

// round 17
// speedup vs baseline: 1.0157x; 1.0157x over previous
#include <cuda_runtime.h>
#include <cuda_bf16.h>
#include <math.h>
#include <stdint.h>
#include <cstdint>

#define N_NODES 10000
#define N_EDGES 160000
#define N_FEAT  512
#define HEADS   8
#define HID     128
#define NH      (HEADS * HID)   // 1024

// ---------------- scratch (device globals; no allocations allowed) ----------
__device__ __nv_bfloat16 g_hb[(size_t)N_NODES * NH]; // projected features bf16
__device__ float g_emb1[(size_t)N_NODES * HID];      // tf32-rounded at write
__device__ float g_emb2[(size_t)N_NODES * HID];
__device__ float g_xr[(size_t)N_NODES * N_FEAT];     // tf32-rounded x
__device__ float g_wr1[NH * N_FEAT];                 // tf32-rounded W1
__device__ float g_wr2[NH * HID];                    // tf32-rounded W2
__device__ float g_si[N_NODES * HEADS];
__device__ float g_sj[N_NODES * HEADS];
__device__ int   g_deg[N_NODES];     // zero at entry; scan re-zeroes after use
__device__ int   g_off[N_NODES + 1];
__device__ int   g_cur[N_NODES];
__device__ int   g_csr[N_EDGES];
__device__ float g_gvec[HID];        // zero at entry; mlp re-zeroes after use

__device__ __forceinline__ unsigned cvt_tf32(float f) {
    unsigned u;
    asm("cvt.rna.tf32.f32 %0, %1;" : "=r"(u) : "f"(f));
    return u;
}

// ---------------- tf32 pre-rounding (x, W1, W2 in ONE launch) ---------------
#define XQ (N_NODES * N_FEAT / 4)
#define W1Q (NH * N_FEAT / 4)
#define W2Q (NH * HID / 4)

__global__ void round_all_kernel(const float* __restrict__ x,
                                 const float* __restrict__ W1,
                                 const float* __restrict__ W2) {
    int i = blockIdx.x * blockDim.x + threadIdx.x;
    const float* src;
    float* dst;
    int k;
    if (i < XQ)            { src = x;  dst = g_xr;  k = i; }
    else if (i < XQ + W1Q) { src = W1; dst = g_wr1; k = i - XQ; }
    else if (i < XQ + W1Q + W2Q) { src = W2; dst = g_wr2; k = i - XQ - W1Q; }
    else return;
    float4 v = reinterpret_cast<const float4*>(src)[k];
    v.x = __uint_as_float(cvt_tf32(v.x));
    v.y = __uint_as_float(cvt_tf32(v.y));
    v.z = __uint_as_float(cvt_tf32(v.z));
    v.w = __uint_as_float(cvt_tf32(v.w));
    reinterpret_cast<float4*>(dst)[k] = v;
}

// ---------------- CSR construction ----------------
__global__ void hist_kernel(const int* __restrict__ dst) {
    int e = blockIdx.x * blockDim.x + threadIdx.x;
    if (e < N_EDGES) atomicAdd(&g_deg[dst[e]], 1);
}

__global__ void scan_kernel() {
    __shared__ int sums[1024];
    int t = threadIdx.x;
    const int CH = (N_NODES + 1023) / 1024;   // 10
    int start = t * CH;
    int dloc[CH];
    int s = 0;
    for (int i = 0; i < CH; i++) {
        int idx = start + i;
        dloc[i] = (idx < N_NODES) ? g_deg[idx] : 0;
        s += dloc[i];
    }
    sums[t] = s;
    __syncthreads();
    for (int st = 1; st < 1024; st <<= 1) {
        int v = (t >= st) ? sums[t - st] : 0;
        __syncthreads();
        sums[t] += v;
        __syncthreads();
    }
    int base = (t == 0) ? 0 : sums[t - 1];
    for (int i = 0; i < CH; i++) {
        int idx = start + i;
        if (idx < N_NODES) {
            g_off[idx] = base;
            g_cur[idx] = base;
            base += dloc[i];
            g_deg[idx] = 0;          // restore invariant for next call
        }
    }
    if (t == 1023) g_off[N_NODES] = sums[1023];
}

__global__ void fill_kernel(const int* __restrict__ src, const int* __restrict__ dst) {
    int e = blockIdx.x * blockDim.x + threadIdx.x;
    if (e < N_EDGES) {
        int pos = atomicAdd(&g_cur[dst[e]], 1);
        g_csr[pos] = src[e];
    }
}

// ---------------- TF32 GEMM (pre-rounded inputs, no in-loop CVT) -----------
// C[m,n] = sum_k A[m,k]*B[n,k]. Block tile 128x128 (one head per x-block),
// 256 threads = 8 warps (4x2), warp tile 32x64, BK=16 double-buffered
// cp.async. __launch_bounds__(256,2) caps regs at 128 -> 2 CTAs/SM.
#define GBM 128
#define GBN 128
#define GBK 16

__device__ __forceinline__ int swoff(int m, int k) {
    return m * GBK + ((((k >> 2) ^ (m >> 1)) & 3) << 2) + (k & 3);
}

__device__ __forceinline__ void mma_tf32(float* c, const unsigned* a, const unsigned* b) {
    asm volatile(
        "mma.sync.aligned.m16n8k8.row.col.f32.tf32.tf32.f32 "
        "{%0,%1,%2,%3}, {%4,%5,%6,%7}, {%8,%9}, {%0,%1,%2,%3};"
        : "+f"(c[0]), "+f"(c[1]), "+f"(c[2]), "+f"(c[3])
        : "r"(a[0]), "r"(a[1]), "r"(a[2]), "r"(a[3]), "r"(b[0]), "r"(b[1]));
}

template<bool LAYER1>
__global__ __launch_bounds__(256, 2)
void gemm_tf32(const float* __restrict__ av, int M, int N, int K) {
    const float* A = LAYER1 ? g_xr  : g_emb1;
    const float* B = LAYER1 ? g_wr1 : g_wr2;

    __shared__ float As[2][GBM * GBK];
    __shared__ float Bs[2][GBM * GBK];
    __shared__ float sh_a[2 * HID];
    __shared__ float sc_i[GBM];
    __shared__ float sc_j[GBM];

    int tid = threadIdx.x;
    int lane = tid & 31;
    int wid = tid >> 5;
    int wm = wid & 3;          // 0..3
    int wn = wid >> 2;         // 0..1
    int bm = blockIdx.y * GBM;
    int bn = blockIdx.x * GBN;
    int head = blockIdx.x;     // GBN == HID => one head per x-block

    if (tid < 2 * HID) sh_a[tid] = av[head * 2 * HID + tid];
    if (tid < GBM) { sc_i[tid] = 0.f; sc_j[tid] = 0.f; }

    unsigned sA = (unsigned)__cvta_generic_to_shared(&As[0][0]);
    unsigned sB = (unsigned)__cvta_generic_to_shared(&Bs[0][0]);

    float acc[2][8][4];
    #pragma unroll
    for (int mi = 0; mi < 2; mi++)
        #pragma unroll
        for (int ni = 0; ni < 8; ni++)
            #pragma unroll
            for (int r = 0; r < 4; r++) acc[mi][ni][r] = 0.f;

    const int nch = K / GBK;

    auto load_tile = [&](int c, int s) {
        #pragma unroll
        for (int i = 0; i < 2; i++) {
            int id  = tid + i * 256;     // 0..511
            int row = id >> 2;           // 0..127
            int g   = id & 3;
            int soff = (s * (GBM * GBK) + row * GBK + (((g ^ (row >> 1)) & 3) << 2)) << 2;
            {
                int gm = bm + row;
                const float* src = A + (size_t)(gm < M ? gm : (M - 1)) * K + c * GBK + g * 4;
                int sz = (gm < M) ? 16 : 0;
                asm volatile("cp.async.cg.shared.global [%0], [%1], 16, %2;\n"
                             :: "r"(sA + soff), "l"(src), "r"(sz));
            }
            {
                const float* src = B + (size_t)(bn + row) * K + c * GBK + g * 4;
                asm volatile("cp.async.cg.shared.global [%0], [%1], 16;\n"
                             :: "r"(sB + soff), "l"(src));
            }
        }
    };

    load_tile(0, 0);
    asm volatile("cp.async.commit_group;\n");

    for (int c = 0; c < nch; c++) {
        int buf = c & 1;
        if (c + 1 < nch) {
            load_tile(c + 1, buf ^ 1);
            asm volatile("cp.async.commit_group;\n");
            asm volatile("cp.async.wait_group 1;\n");
        } else {
            asm volatile("cp.async.wait_group 0;\n");
        }
        __syncthreads();

        #pragma unroll
        for (int ks = 0; ks < GBK / 8; ks++) {
            int kk = ks * 8 + (lane & 3);
            unsigned af[2][4];
            #pragma unroll
            for (int mi = 0; mi < 2; mi++) {
                int m0 = wm * 32 + mi * 16 + (lane >> 2);
                int m1 = m0 + 8;
                af[mi][0] = __float_as_uint(As[buf][swoff(m0, kk)]);
                af[mi][1] = __float_as_uint(As[buf][swoff(m1, kk)]);
                af[mi][2] = __float_as_uint(As[buf][swoff(m0, kk + 4)]);
                af[mi][3] = __float_as_uint(As[buf][swoff(m1, kk + 4)]);
            }
            unsigned bf[8][2];
            #pragma unroll
            for (int ni = 0; ni < 8; ni++) {
                int n0 = wn * 64 + ni * 8 + (lane >> 2);
                bf[ni][0] = __float_as_uint(Bs[buf][swoff(n0, kk)]);
                bf[ni][1] = __float_as_uint(Bs[buf][swoff(n0, kk + 4)]);
            }
            #pragma unroll
            for (int mi = 0; mi < 2; mi++)
                #pragma unroll
                for (int ni = 0; ni < 8; ni++)
                    mma_tf32(acc[mi][ni], af[mi], bf[ni]);
        }
        __syncthreads();
    }

    // ---- epilogue: bf16 store + fused score partials -----------------------
    float sco[2][4];   // per mi: si(m0), si(m1), sj(m0), sj(m1)
    #pragma unroll
    for (int mi = 0; mi < 2; mi++)
        #pragma unroll
        for (int r = 0; r < 4; r++) sco[mi][r] = 0.f;

    #pragma unroll
    for (int mi = 0; mi < 2; mi++) {
        int m0 = bm + wm * 32 + mi * 16 + (lane >> 2);
        int m1 = m0 + 8;
        #pragma unroll
        for (int ni = 0; ni < 8; ni++) {
            int dloc = wn * 64 + ni * 8 + (lane & 3) * 2;   // 0..127 within head
            float ai0 = sh_a[dloc],       ai1 = sh_a[dloc + 1];
            float aj0 = sh_a[HID + dloc], aj1 = sh_a[HID + dloc + 1];
            sco[mi][0] += acc[mi][ni][0] * ai0 + acc[mi][ni][1] * ai1;
            sco[mi][1] += acc[mi][ni][2] * ai0 + acc[mi][ni][3] * ai1;
            sco[mi][2] += acc[mi][ni][0] * aj0 + acc[mi][ni][1] * aj1;
            sco[mi][3] += acc[mi][ni][2] * aj0 + acc[mi][ni][3] * aj1;
            int nc = bn + dloc;
            if (m0 < M) {
                __nv_bfloat162 hb = __floats2bfloat162_rn(acc[mi][ni][0], acc[mi][ni][1]);
                *reinterpret_cast<__nv_bfloat162*>(&g_hb[(size_t)m0 * N + nc]) = hb;
            }
            if (m1 < M) {
                __nv_bfloat162 hb = __floats2bfloat162_rn(acc[mi][ni][2], acc[mi][ni][3]);
                *reinterpret_cast<__nv_bfloat162*>(&g_hb[(size_t)m1 * N + nc]) = hb;
            }
        }
    }

    #pragma unroll
    for (int mi = 0; mi < 2; mi++)
        #pragma unroll
        for (int r = 0; r < 4; r++) {
            sco[mi][r] += __shfl_xor_sync(0xffffffffu, sco[mi][r], 1);
            sco[mi][r] += __shfl_xor_sync(0xffffffffu, sco[mi][r], 2);
        }

    if ((lane & 3) == 0) {
        #pragma unroll
        for (int mi = 0; mi < 2; mi++) {
            int r0 = wm * 32 + mi * 16 + (lane >> 2);
            int r1 = r0 + 8;
            atomicAdd(&sc_i[r0], sco[mi][0]);
            atomicAdd(&sc_i[r1], sco[mi][1]);
            atomicAdd(&sc_j[r0], sco[mi][2]);
            atomicAdd(&sc_j[r1], sco[mi][3]);
        }
    }
    __syncthreads();

    if (tid < GBM) {
        int gm = bm + tid;
        if (gm < M) {
            g_si[gm * HEADS + head] = sc_i[tid];
            g_sj[gm * HEADS + head] = sc_j[tid];
        }
    }
}

// ---------------- aggregation: single-pass softmax + bf16 gather -----------
template<int OUT>
__global__ __launch_bounds__(256)
void aggregate_kernel() {
    int n = blockIdx.x;
    int w = threadIdx.x >> 5;
    int lane = threadIdx.x & 31;
    __shared__ float part[HEADS][HID];

    int off = g_off[n], end = g_off[n + 1];
    float si_v = g_si[n * HEADS + w];
    float4 acc = make_float4(0.f, 0.f, 0.f, 0.f);
    float dl = 0.f;

    for (int base = off; base < end; base += 32) {
        int e = base + lane;
        int src = 0;
        float p = 0.f;
        if (e < end) {
            src = g_csr[e];
            float x = si_v + g_sj[src * HEADS + w];
            float ev = (x > 0.f) ? x : 0.01f * x;
            p = __expf(ev);
            dl += p;
        }

        int cnt = min(32, end - base);
        const size_t lofs = (size_t)lane * 4;
        int j = 0;
        for (; j + 4 <= cnt; j += 4) {
            float p0 = __shfl_sync(0xffffffffu, p, j);
            float p1 = __shfl_sync(0xffffffffu, p, j + 1);
            float p2 = __shfl_sync(0xffffffffu, p, j + 2);
            float p3 = __shfl_sync(0xffffffffu, p, j + 3);
            int s0 = __shfl_sync(0xffffffffu, src, j);
            int s1 = __shfl_sync(0xffffffffu, src, j + 1);
            int s2 = __shfl_sync(0xffffffffu, src, j + 2);
            int s3 = __shfl_sync(0xffffffffu, src, j + 3);
            uint2 u0 = *reinterpret_cast<const uint2*>(&g_hb[((size_t)s0 * HEADS + w) * HID + lofs]);
            uint2 u1 = *reinterpret_cast<const uint2*>(&g_hb[((size_t)s1 * HEADS + w) * HID + lofs]);
            uint2 u2 = *reinterpret_cast<const uint2*>(&g_hb[((size_t)s2 * HEADS + w) * HID + lofs]);
            uint2 u3 = *reinterpret_cast<const uint2*>(&g_hb[((size_t)s3 * HEADS + w) * HID + lofs]);
            float2 a0 = __bfloat1622float2(*reinterpret_cast<__nv_bfloat162*>(&u0.x));
            float2 b0 = __bfloat1622float2(*reinterpret_cast<__nv_bfloat162*>(&u0.y));
            float2 a1 = __bfloat1622float2(*reinterpret_cast<__nv_bfloat162*>(&u1.x));
            float2 b1 = __bfloat1622float2(*reinterpret_cast<__nv_bfloat162*>(&u1.y));
            float2 a2f = __bfloat1622float2(*reinterpret_cast<__nv_bfloat162*>(&u2.x));
            float2 b2 = __bfloat1622float2(*reinterpret_cast<__nv_bfloat162*>(&u2.y));
            float2 a3 = __bfloat1622float2(*reinterpret_cast<__nv_bfloat162*>(&u3.x));
            float2 b3 = __bfloat1622float2(*reinterpret_cast<__nv_bfloat162*>(&u3.y));
            acc.x += p0 * a0.x + p1 * a1.x + p2 * a2f.x + p3 * a3.x;
            acc.y += p0 * a0.y + p1 * a1.y + p2 * a2f.y + p3 * a3.y;
            acc.z += p0 * b0.x + p1 * b1.x + p2 * b2.x  + p3 * b3.x;
            acc.w += p0 * b0.y + p1 * b1.y + p2 * b2.y  + p3 * b3.y;
        }
        for (; j < cnt; j++) {
            float pj = __shfl_sync(0xffffffffu, p, j);
            int sj = __shfl_sync(0xffffffffu, src, j);
            uint2 u = *reinterpret_cast<const uint2*>(&g_hb[((size_t)sj * HEADS + w) * HID + lofs]);
            float2 f0 = __bfloat1622float2(*reinterpret_cast<__nv_bfloat162*>(&u.x));
            float2 f1 = __bfloat1622float2(*reinterpret_cast<__nv_bfloat162*>(&u.y));
            acc.x += pj * f0.x; acc.y += pj * f0.y;
            acc.z += pj * f1.x; acc.w += pj * f1.y;
        }
    }

    #pragma unroll
    for (int o = 16; o; o >>= 1) dl += __shfl_xor_sync(0xffffffffu, dl, o);

    if (dl > 0.f) {
        float inv = 1.f / dl;
        acc.x *= inv; acc.y *= inv; acc.z *= inv; acc.w *= inv;
    }
    part[w][lane * 4 + 0] = acc.x;
    part[w][lane * 4 + 1] = acc.y;
    part[w][lane * 4 + 2] = acc.z;
    part[w][lane * 4 + 3] = acc.w;
    __syncthreads();

    if (threadIdx.x < HID) {
        int d = threadIdx.x;
        float s = 0.f;
        #pragma unroll
        for (int hh = 0; hh < HEADS; hh++) s += part[hh][d];
        s *= (1.f / HEADS);
        float o = (s > 0.f) ? s : (__expf(s) - 1.f);   // ELU
        if (OUT == 1) {
            // emb1 feeds GEMM2's A operand: pre-round to tf32 (rna) here
            o = __uint_as_float(cvt_tf32(o));
            g_emb1[(size_t)n * HID + d] = o;
        } else {
            g_emb2[(size_t)n * HID + d] = o;
        }
    }
}

// ---------------- graph mean pooling (one kernel, atomic combine) ----------
__global__ void pool_kernel() {
    const int RP = (N_NODES + 127) / 128;   // 79
    int b = blockIdx.x, d = threadIdx.x;
    int r0 = b * RP;
    int r1 = min(r0 + RP, N_NODES);
    float s = 0.f;
    for (int r = r0; r < r1; r++) s += g_emb2[(size_t)r * HID + d];
    atomicAdd(&g_gvec[d], s * (1.f / N_NODES));
}

// ---------------- MLP head ----------------
__global__ void mlp_kernel(const float* __restrict__ ln_g, const float* __restrict__ ln_b,
                           const float* __restrict__ Wl1, const float* __restrict__ bl1,
                           const float* __restrict__ Wl2, const float* __restrict__ bl2,
                           const float* __restrict__ Wl3, const float* __restrict__ bl3,
                           float* __restrict__ out) {
    __shared__ float gn[HID];
    __shared__ float x1[64];
    __shared__ float x2[16];
    __shared__ float red[128];
    int t = threadIdx.x;  // 128 threads
    float gv = g_gvec[t];
    g_gvec[t] = 0.f;      // restore invariant for next call

    red[t] = gv;
    __syncthreads();
    for (int st = 64; st; st >>= 1) {
        if (t < st) red[t] += red[t + st];
        __syncthreads();
    }
    float mu = red[0] * (1.f / HID);
    __syncthreads();

    float dv = gv - mu;
    red[t] = dv * dv;
    __syncthreads();
    for (int st = 64; st; st >>= 1) {
        if (t < st) red[t] += red[t + st];
        __syncthreads();
    }
    float var = red[0] * (1.f / HID);
    gn[t] = dv * rsqrtf(var + 1e-5f) * ln_g[t] + ln_b[t];
    __syncthreads();

    if (t < 64) {
        float s = bl1[t];
        for (int k = 0; k < HID; k++) s += Wl1[t * HID + k] * gn[k];
        x1[t] = (s > 0.f) ? s : 0.01f * s;
    }
    __syncthreads();
    if (t < 16) {
        float s = bl2[t];
        for (int k = 0; k < 64; k++) s += Wl2[t * 64 + k] * x1[k];
        x2[t] = (s > 0.f) ? s : 0.01f * s;
    }
    __syncthreads();
    if (t < 16) {
        float s = bl3[t];
        for (int k = 0; k < 16; k++) s += Wl3[t * 16 + k] * x2[k];
        out[t] = fmaxf(s, 0.f);
    }
}

// ---------------- launch ----------------
extern "C" void kernel_launch(void* const* d_in, const int* in_sizes, int n_in,
                              void* d_out, int out_size) {
    const float* x    = (const float*)d_in[0];
    const int*   esrc = (const int*)  d_in[1];
    const int*   edst = (const int*)  d_in[2];
    const float* W1   = (const float*)d_in[3];
    const float* a1   = (const float*)d_in[4];
    const float* W2   = (const float*)d_in[5];
    const float* a2   = (const float*)d_in[6];
    const float* ln_g = (const float*)d_in[7];
    const float* ln_b = (const float*)d_in[8];
    const float* Wl1  = (const float*)d_in[9];
    const float* bl1  = (const float*)d_in[10];
    const float* Wl2  = (const float*)d_in[11];
    const float* bl2  = (const float*)d_in[12];
    const float* Wl3  = (const float*)d_in[13];
    const float* bl3  = (const float*)d_in[14];
    float* out = (float*)d_out;

    // tf32 pre-rounding (rna) of all GEMM inputs, one launch
    const int totq = XQ + W1Q + W2Q;
    round_all_kernel<<<(totq + 255) / 256, 256>>>(x, W1, W2);

    // CSR build (g_deg is zero at entry; scan restores it)
    hist_kernel<<<(N_EDGES + 255) / 256, 256>>>(edst);
    scan_kernel<<<1, 1024>>>();
    fill_kernel<<<(N_EDGES + 255) / 256, 256>>>(esrc, edst);

    dim3 ggrid(NH / GBN, (N_NODES + GBM - 1) / GBM);   // (8, 79)

    // Layer 1
    gemm_tf32<true><<<ggrid, 256>>>(a1, N_NODES, NH, N_FEAT);
    aggregate_kernel<1><<<N_NODES, 256>>>();

    // Layer 2
    gemm_tf32<false><<<ggrid, 256>>>(a2, N_NODES, NH, HID);
    aggregate_kernel<2><<<N_NODES, 256>>>();

    // Pool + head
    pool_kernel<<<128, 128>>>();
    mlp_kernel<<<1, 128>>>(ln_g, ln_b, Wl1, bl1, Wl2, bl2, Wl3, bl3, out);
}